// round 13
// baseline (speedup 1.0000x reference)
#include <cuda_runtime.h>
#include <cuda_fp16.h>
#include <math.h>

#define NN 100000
#define EE 3200000
#define GG 64

// ---------------- static device scratch (zero-initialized at module load) ----------------
__device__ float4 g_x4[NN];          // padded x
__device__ float4 g_cf[NN * 4];      // per (node,head): (e0,e1,e2,d0) pre-scaled
__device__ float4 g_ds[NN * 4];      // per (node,head): (den, sx0, sx1, sx2)

__device__ __half g_kvh[NN * 16];    // 32B/node: [0..5]=k2 half, [6..11]=v2 half, pad
__device__ float  g_qs[NN * 16];     // [0..5]=q2 (pre-scaled), [8..13]=s2

__device__ int g_deg   [NN];         // invariant: zero on kernel_launch entry
__device__ int g_rowptr[NN + 1];
__device__ int g_rank  [EE];
__device__ int g_csrsrc[EE];
__device__ volatile int g_bsum[128]; // invariant: zero on entry (0 = not ready; stores sum+1)
__device__ int g_ticket;             // invariant: zero on entry

__device__ float g_sums[GG * 6];     // invariant: zero on entry
__device__ float g_cnt [GG];         // invariant: zero on entry

// ---------------- fused prep + hist ----------------
__global__ void k_prep_hist(const float* __restrict__ x,
                            const int* __restrict__ dst,
                            const float* __restrict__ Wq, const float* __restrict__ bq,
                            const float* __restrict__ Wk, const float* __restrict__ bk,
                            int n, int e) {
    int idx = blockIdx.x * blockDim.x + threadIdx.x;
    if (idx < e)
        g_rank[idx] = atomicAdd(&g_deg[dst[idx]], 1);
    if (idx >= n * 4) return;
    int node = idx >> 2, h = idx & 3;
    float x0 = __ldg(&x[node * 3 + 0]);
    float x1 = __ldg(&x[node * 3 + 1]);
    float x2 = __ldg(&x[node * 3 + 2]);
    if (h == 0)
        g_x4[node] = make_float4(x0, x1, x2, 0.f);
    float d0 = 0.f, e0 = 0.f, e1 = 0.f, e2 = 0.f;
    int base = h * 16;
#pragma unroll
    for (int c = 0; c < 16; c++) {
        int cc = base + c;
        float qc = bq[cc] + x0 * Wq[cc] + x1 * Wq[64 + cc] + x2 * Wq[128 + cc];
        d0 += qc * bk[cc];
        e0 += qc * Wk[cc];
        e1 += qc * Wk[64 + cc];
        e2 += qc * Wk[128 + cc];
    }
    g_cf[idx] = make_float4(e0 * 0.25f, e1 * 0.25f, e2 * 0.25f, d0 * 0.25f);
}

// ---------------- single-kernel decoupled-lookback scan ----------------
__global__ void __launch_bounds__(1024) k_scan(int n, int e) {
    __shared__ int wsum[32];
    __shared__ int sboff;
    int lane = threadIdx.x & 31, wid = threadIdx.x >> 5;
    int blk = blockIdx.x;

    int i = blk * 1024 + threadIdx.x;
    int v = (i < n) ? g_deg[i] : 0;
    int x = v;
#pragma unroll
    for (int off = 1; off < 32; off <<= 1) {
        int y = __shfl_up_sync(0xFFFFFFFFu, x, off);
        if (lane >= off) x += y;
    }
    if (lane == 31) wsum[wid] = x;
    __syncthreads();
    if (wid == 0) {
        int w = wsum[lane];
#pragma unroll
        for (int off = 1; off < 32; off <<= 1) {
            int y = __shfl_up_sync(0xFFFFFFFFu, w, off);
            if (lane >= off) w += y;
        }
        wsum[lane] = w;
        if (lane == 31) {
            g_bsum[blk] = w + 1;     // publish block total (+1 sentinel offset)
            __threadfence();
        }
    }
    __syncthreads();

    if (wid == 0) {
        int acc = 0;
        for (int j = lane; j < blk; j += 32) {
            int t;
            do { t = g_bsum[j]; } while (t == 0);
            acc += t - 1;
        }
#pragma unroll
        for (int off = 16; off > 0; off >>= 1)
            acc += __shfl_xor_sync(0xFFFFFFFFu, acc, off);
        if (lane == 0) sboff = acc;
    }
    __syncthreads();

    int excl = x - v + ((wid > 0) ? wsum[wid - 1] : 0) + sboff;
    if (i < n) { g_rowptr[i] = excl; g_deg[i] = 0; }
    if (i == n) g_rowptr[n] = e;
}

// ---------------- scatter (rank-based, no atomics); also resets g_bsum ----------------
__global__ void k_scatter(const int* __restrict__ src, const int* __restrict__ dst, int e) {
    int i = blockIdx.x * blockDim.x + threadIdx.x;
    if (blockIdx.x == 0 && threadIdx.x < 128)
        g_bsum[threadIdx.x] = 0;
    if (i >= e) return;
    int p = g_rowptr[dst[i]] + g_rank[i];
    g_csrsrc[p] = src[i];
}

// ---------------- attention layer 1: 8 lanes/node, prefetched (kept from R12) ----------------
__global__ void k_attn1(int n) {
    int gt = blockIdx.x * blockDim.x + threadIdx.x;
    int node = gt >> 3;
    int sub = gt & 7;
    bool valid = (node < n);

    float4 cf0, cf1, cf2, cf3;
    int beg = 0, end = 0;
    if (valid) {
        cf0 = g_cf[node * 4 + 0];
        cf1 = g_cf[node * 4 + 1];
        cf2 = g_cf[node * 4 + 2];
        cf3 = g_cf[node * 4 + 3];
        beg = g_rowptr[node];
        end = g_rowptr[node + 1];
    }

    float4 ds0 = make_float4(0.f, 0.f, 0.f, 0.f);
    float4 ds1 = make_float4(0.f, 0.f, 0.f, 0.f);
    float4 ds2 = make_float4(0.f, 0.f, 0.f, 0.f);
    float4 ds3 = make_float4(0.f, 0.f, 0.f, 0.f);

    int i = beg + sub;
    float4 xs_c = make_float4(0.f, 0.f, 0.f, 0.f);
    if (i < end) xs_c = g_x4[g_csrsrc[i]];
    while (i < end) {
        int i2 = i + 8;
        float4 xs_n;
        if (i2 < end) xs_n = g_x4[g_csrsrc[i2]];
        float4 xs = xs_c;
        float w0 = __expf(cf0.w + cf0.x * xs.x + cf0.y * xs.y + cf0.z * xs.z);
        float w1 = __expf(cf1.w + cf1.x * xs.x + cf1.y * xs.y + cf1.z * xs.z);
        float w2 = __expf(cf2.w + cf2.x * xs.x + cf2.y * xs.y + cf2.z * xs.z);
        float w3 = __expf(cf3.w + cf3.x * xs.x + cf3.y * xs.y + cf3.z * xs.z);
        ds0.x += w0; ds0.y += w0 * xs.x; ds0.z += w0 * xs.y; ds0.w += w0 * xs.z;
        ds1.x += w1; ds1.y += w1 * xs.x; ds1.z += w1 * xs.y; ds1.w += w1 * xs.z;
        ds2.x += w2; ds2.y += w2 * xs.x; ds2.z += w2 * xs.y; ds2.w += w2 * xs.z;
        ds3.x += w3; ds3.y += w3 * xs.x; ds3.z += w3 * xs.y; ds3.w += w3 * xs.z;
        xs_c = xs_n;
        i = i2;
    }

#pragma unroll
    for (int off = 1; off <= 4; off <<= 1) {
        ds0.x += __shfl_xor_sync(0xFFFFFFFFu, ds0.x, off);
        ds0.y += __shfl_xor_sync(0xFFFFFFFFu, ds0.y, off);
        ds0.z += __shfl_xor_sync(0xFFFFFFFFu, ds0.z, off);
        ds0.w += __shfl_xor_sync(0xFFFFFFFFu, ds0.w, off);
        ds1.x += __shfl_xor_sync(0xFFFFFFFFu, ds1.x, off);
        ds1.y += __shfl_xor_sync(0xFFFFFFFFu, ds1.y, off);
        ds1.z += __shfl_xor_sync(0xFFFFFFFFu, ds1.z, off);
        ds1.w += __shfl_xor_sync(0xFFFFFFFFu, ds1.w, off);
        ds2.x += __shfl_xor_sync(0xFFFFFFFFu, ds2.x, off);
        ds2.y += __shfl_xor_sync(0xFFFFFFFFu, ds2.y, off);
        ds2.z += __shfl_xor_sync(0xFFFFFFFFu, ds2.z, off);
        ds2.w += __shfl_xor_sync(0xFFFFFFFFu, ds2.w, off);
        ds3.x += __shfl_xor_sync(0xFFFFFFFFu, ds3.x, off);
        ds3.y += __shfl_xor_sync(0xFFFFFFFFu, ds3.y, off);
        ds3.z += __shfl_xor_sync(0xFFFFFFFFu, ds3.z, off);
        ds3.w += __shfl_xor_sync(0xFFFFFFFFu, ds3.w, off);
    }

    if (valid && sub < 4) {
        float4 myds = (sub == 0) ? ds0 : (sub == 1) ? ds1 : (sub == 2) ? ds2 : ds3;
        g_ds[node * 4 + sub] = myds;
    }
}

// ---------------- layer 2 projection: 32 nodes/block, fused layer-1 epilogue ----------------
__global__ void __launch_bounds__(1024)
k_gemm2(const float* __restrict__ Wv1, const float* __restrict__ bv1,
        const float* __restrict__ Ws1, const float* __restrict__ bs1,
        const float* __restrict__ Wq, const float* __restrict__ bq,
        const float* __restrict__ Wk, const float* __restrict__ bk,
        const float* __restrict__ Wv, const float* __restrict__ bv,
        const float* __restrict__ Ws, const float* __restrict__ bs,
        int n) {
    __shared__ float  shH[32][64];
    __shared__ float  shW2[4][390];
    __shared__ float  shB2[4][6];
    __shared__ float  shWv[192], shBv[64], shWs[192], shBs[64];
    __shared__ float4 shDS[128];
    __shared__ float4 shX[32];
    int tid = threadIdx.x;
    int blk = blockIdx.x;

    for (int i = tid; i < 384 * 4; i += 1024) {
        int mm = i / 384, r = i % 384;
        const float* W = (mm == 0) ? Wq : (mm == 1) ? Wk : (mm == 2) ? Wv : Ws;
        shW2[mm][r] = W[r];
    }
    if (tid < 24) {
        int mm = tid / 6, cc = tid % 6;
        const float* b = (mm == 0) ? bq : (mm == 1) ? bk : (mm == 2) ? bv : bs;
        shB2[mm][cc] = b[cc];
    }
    if (tid < 192) { shWv[tid] = Wv1[tid]; shWs[tid] = Ws1[tid]; }
    else if (tid < 256) { shBv[tid - 192] = bv1[tid - 192]; shBs[tid - 192] = bs1[tid - 192]; }
    if (tid < 128) {
        int gidx = blk * 128 + tid;
        shDS[tid] = (gidx < n * 4) ? g_ds[gidx] : make_float4(0.f, 0.f, 0.f, 0.f);
    }
    if (tid < 32) {
        int node = blk * 32 + tid;
        shX[tid] = (node < n) ? g_x4[node] : make_float4(0.f, 0.f, 0.f, 0.f);
    }
    __syncthreads();

#pragma unroll
    for (int r = 0; r < 2; r++) {
        int idx = tid + r * 1024;
        int local = idx >> 6, c = idx & 63;
        float4 ds = shDS[local * 4 + (c >> 4)];
        float4 xt = shX[local];
        float num = shBv[c] * ds.x + shWv[c] * ds.y + shWv[64 + c] * ds.z + shWv[128 + c] * ds.w;
        float val = num / (ds.x + 1e-16f)
                  + shBs[c] + xt.x * shWs[c] + xt.y * shWs[64 + c] + xt.z * shWs[128 + c];
        shH[local][c] = fmaxf(val, 0.f);
    }
    __syncthreads();

    int w = tid >> 5;
    int lane = tid & 31;
    int node = blk * 32 + w;
    if (node >= n || lane >= 24) return;
    int mm = lane / 6, cc = lane % 6;
    float acc = shB2[mm][cc];
#pragma unroll
    for (int k = 0; k < 64; k++) acc += shH[w][k] * shW2[mm][k * 6 + cc];
    if (mm == 0)      g_qs[node * 16 + cc]      = acc * 0.4082482904638631f;
    else if (mm == 1) g_kvh[node * 16 + cc]     = __float2half(acc);
    else if (mm == 2) g_kvh[node * 16 + 6 + cc] = __float2half(acc);
    else              g_qs[node * 16 + 8 + cc]  = acc;
}

// ---------------- attention layer 2 + pooling + output (4 lanes/node, ticket) ----------------
__global__ void k_attn2_pool(const int* __restrict__ batch, int n, float* __restrict__ out) {
    __shared__ float ssum[GG * 6];
    __shared__ float scnt[GG];
    __shared__ int   sflag[GG];
    __shared__ int   slast;
    int tid = threadIdx.x;
    for (int i = tid; i < GG * 6; i += blockDim.x) ssum[i] = 0.f;
    for (int i = tid; i < GG; i += blockDim.x) { scnt[i] = 0.f; sflag[i] = 0; }
    __syncthreads();

    int gt = blockIdx.x * blockDim.x + tid;
    int node = gt >> 2;
    int sub = gt & 3;
    bool valid = (node < n);

    float4 qa = make_float4(0.f, 0.f, 0.f, 0.f);
    float2 qb = make_float2(0.f, 0.f);
    int beg = 0, end = 0;
    if (valid) {
        qa = *reinterpret_cast<const float4*>(g_qs + node * 16);
        qb = *reinterpret_cast<const float2*>(g_qs + node * 16 + 4);
        beg = g_rowptr[node];
        end = g_rowptr[node + 1];
    }

    const uint4* kv = reinterpret_cast<const uint4*>(g_kvh);

    float den = 0.f;
    float a0 = 0.f, a1 = 0.f, a2 = 0.f, a3 = 0.f, a4 = 0.f, a5 = 0.f;

    int i = beg + sub;
    uint4 r0c = make_uint4(0, 0, 0, 0), r1c = make_uint4(0, 0, 0, 0);
    if (i < end) {
        int s = g_csrsrc[i];
        r0c = __ldg(&kv[s * 2 + 0]);
        r1c = __ldg(&kv[s * 2 + 1]);
    }
    while (i < end) {
        int i2 = i + 4;
        uint4 r0n, r1n;
        if (i2 < end) {
            int s2 = g_csrsrc[i2];
            r0n = __ldg(&kv[s2 * 2 + 0]);
            r1n = __ldg(&kv[s2 * 2 + 1]);
        }
        float2 k01 = __half22float2(*reinterpret_cast<const __half2*>(&r0c.x));
        float2 k23 = __half22float2(*reinterpret_cast<const __half2*>(&r0c.y));
        float2 k45 = __half22float2(*reinterpret_cast<const __half2*>(&r0c.z));
        float2 v01 = __half22float2(*reinterpret_cast<const __half2*>(&r0c.w));
        float2 v23 = __half22float2(*reinterpret_cast<const __half2*>(&r1c.x));
        float2 v45 = __half22float2(*reinterpret_cast<const __half2*>(&r1c.y));
        float l = qa.x * k01.x + qa.y * k01.y + qa.z * k23.x + qa.w * k23.y
                + qb.x * k45.x + qb.y * k45.y;
        float w = __expf(l);
        den += w;
        a0 += w * v01.x; a1 += w * v01.y;
        a2 += w * v23.x; a3 += w * v23.y;
        a4 += w * v45.x; a5 += w * v45.y;
        r0c = r0n; r1c = r1n;
        i = i2;
    }

#pragma unroll
    for (int off = 1; off <= 2; off <<= 1) {
        den += __shfl_xor_sync(0xFFFFFFFFu, den, off);
        a0 += __shfl_xor_sync(0xFFFFFFFFu, a0, off);
        a1 += __shfl_xor_sync(0xFFFFFFFFu, a1, off);
        a2 += __shfl_xor_sync(0xFFFFFFFFu, a2, off);
        a3 += __shfl_xor_sync(0xFFFFFFFFu, a3, off);
        a4 += __shfl_xor_sync(0xFFFFFFFFu, a4, off);
        a5 += __shfl_xor_sync(0xFFFFFFFFu, a5, off);
    }

    if (valid && sub == 0) {
        float inv = 1.f / (den + 1e-16f);
        int g = __ldg(&batch[node]);
        const float* sp = g_qs + node * 16 + 8;
        atomicAdd(&ssum[g * 6 + 0], a0 * inv + sp[0]);
        atomicAdd(&ssum[g * 6 + 1], a1 * inv + sp[1]);
        atomicAdd(&ssum[g * 6 + 2], a2 * inv + sp[2]);
        atomicAdd(&ssum[g * 6 + 3], a3 * inv + sp[3]);
        atomicAdd(&ssum[g * 6 + 4], a4 * inv + sp[4]);
        atomicAdd(&ssum[g * 6 + 5], a5 * inv + sp[5]);
        atomicAdd(&scnt[g], 1.f);
        sflag[g] = 1;
    }
    __syncthreads();
    for (int g = tid; g < GG; g += blockDim.x) {
        if (sflag[g]) {
            atomicAdd(&g_cnt[g], scnt[g]);
#pragma unroll
            for (int c = 0; c < 6; c++)
                atomicAdd(&g_sums[g * 6 + c], ssum[g * 6 + c]);
        }
    }
    __syncthreads();
    if (tid == 0) {
        __threadfence();
        int t = atomicAdd(&g_ticket, 1);
        slast = (t == (int)gridDim.x - 1) ? 1 : 0;
    }
    __syncthreads();
    if (slast) {
        __threadfence();
        int g = tid;
        if (g < GG) {
            float cnt = fmaxf(g_cnt[g], 1.f);
            float p[6];
            float m = -INFINITY;
#pragma unroll
            for (int c = 0; c < 6; c++) { p[c] = g_sums[g * 6 + c] / cnt; m = fmaxf(m, p[c]); }
            float s = 0.f;
#pragma unroll
            for (int c = 0; c < 6; c++) s += expf(p[c] - m);
            float lse = m + logf(s);
#pragma unroll
            for (int c = 0; c < 6; c++) out[g * 6 + c] = p[c] - lse;
        }
        __syncthreads();
        for (int i2 = tid; i2 < GG * 6; i2 += blockDim.x) g_sums[i2] = 0.f;
        for (int i2 = tid; i2 < GG; i2 += blockDim.x) g_cnt[i2] = 0.f;
        if (tid == 0) g_ticket = 0;
    }
}

// ---------------- launch ----------------
extern "C" void kernel_launch(void* const* d_in, const int* in_sizes, int n_in,
                              void* d_out, int out_size) {
    const float* x    = (const float*)d_in[0];
    const int*   ei   = (const int*)  d_in[1];
    const int*   batch= (const int*)  d_in[2];
    const float* Wq1  = (const float*)d_in[3];
    const float* bq1  = (const float*)d_in[4];
    const float* Wk1  = (const float*)d_in[5];
    const float* bk1  = (const float*)d_in[6];
    const float* Wv1  = (const float*)d_in[7];
    const float* bv1  = (const float*)d_in[8];
    const float* Ws1  = (const float*)d_in[9];
    const float* bs1  = (const float*)d_in[10];
    const float* Wq2  = (const float*)d_in[11];
    const float* bq2  = (const float*)d_in[12];
    const float* Wk2  = (const float*)d_in[13];
    const float* bk2  = (const float*)d_in[14];
    const float* Wv2  = (const float*)d_in[15];
    const float* bv2  = (const float*)d_in[16];
    const float* Ws2  = (const float*)d_in[17];
    const float* bs2  = (const float*)d_in[18];
    float* out = (float*)d_out;

    int N = in_sizes[0] / 3;
    int E = in_sizes[1] / 2;
    const int* src = ei;
    const int* dst = ei + E;

    const int B = 256;
    int NB = (N + 1024) / 1024;   // covers i == N for rowptr[N]; <= 98 blocks

    k_prep_hist<<<(E + B - 1) / B, B>>>(x, dst, Wq1, bq1, Wk1, bk1, N, E);
    k_scan<<<NB, 1024>>>(N, E);
    k_scatter<<<(E + B - 1) / B, B>>>(src, dst, E);
    k_attn1<<<(N * 8 + B - 1) / B, B>>>(N);
    k_gemm2<<<(N + 31) / 32, 1024>>>(Wv1, bv1, Ws1, bs1,
                                     Wq2, bq2, Wk2, bk2, Wv2, bv2, Ws2, bs2, N);
    k_attn2_pool<<<(N * 4 + B - 1) / B, B>>>(batch, N, out);
}

// round 14
// speedup vs baseline: 1.0137x; 1.0137x over previous
#include <cuda_runtime.h>
#include <cuda_fp16.h>
#include <math.h>

#define NN 100000
#define EE 3200000
#define GG 64

// ---------------- static device scratch (zero-initialized at module load) ----------------
__device__ float4 g_x4[NN];          // padded x
__device__ float4 g_cf[NN * 4];      // per (node,head): (e0,e1,e2,d0) pre-scaled
__device__ float4 g_ds[NN * 4];      // per (node,head): (den, sx0, sx1, sx2)

__device__ __half g_kvh[NN * 16];    // 32B/node: [0..5]=k2 half, [6..11]=v2 half, pad
__device__ float  g_qs[NN * 16];     // [0..5]=q2 (pre-scaled), [8..13]=s2

__device__ int g_deg   [NN];         // invariant: zero on kernel_launch entry
__device__ int g_rowptr[NN + 1];
__device__ int g_rank  [EE];
__device__ int g_csrsrc[EE];
__device__ int g_bsum[128];
__device__ int g_ticket;             // invariant: zero on entry

__device__ float g_sums[GG * 6];     // invariant: zero on entry
__device__ float g_cnt [GG];         // invariant: zero on entry

// ---------------- fused prep + hist ----------------
__global__ void k_prep_hist(const float* __restrict__ x,
                            const int* __restrict__ dst,
                            const float* __restrict__ Wq, const float* __restrict__ bq,
                            const float* __restrict__ Wk, const float* __restrict__ bk,
                            int n, int e) {
    int idx = blockIdx.x * blockDim.x + threadIdx.x;
    if (idx < e)
        g_rank[idx] = atomicAdd(&g_deg[dst[idx]], 1);
    if (idx >= n * 4) return;
    int node = idx >> 2, h = idx & 3;
    float x0 = __ldg(&x[node * 3 + 0]);
    float x1 = __ldg(&x[node * 3 + 1]);
    float x2 = __ldg(&x[node * 3 + 2]);
    if (h == 0)
        g_x4[node] = make_float4(x0, x1, x2, 0.f);
    float d0 = 0.f, e0 = 0.f, e1 = 0.f, e2 = 0.f;
    int base = h * 16;
#pragma unroll
    for (int c = 0; c < 16; c++) {
        int cc = base + c;
        float qc = bq[cc] + x0 * Wq[cc] + x1 * Wq[64 + cc] + x2 * Wq[128 + cc];
        d0 += qc * bk[cc];
        e0 += qc * Wk[cc];
        e1 += qc * Wk[64 + cc];
        e2 += qc * Wk[128 + cc];
    }
    g_cf[idx] = make_float4(e0 * 0.25f, e1 * 0.25f, e2 * 0.25f, d0 * 0.25f);
}

// ---------------- two-kernel scan (restored from R11) ----------------
__global__ void k_scan_blk(int n) {
    __shared__ int wsum[32];
    int i = blockIdx.x * 1024 + threadIdx.x;
    int v = (i < n) ? g_deg[i] : 0;
#pragma unroll
    for (int off = 16; off > 0; off >>= 1)
        v += __shfl_xor_sync(0xFFFFFFFFu, v, off);
    int lane = threadIdx.x & 31, wid = threadIdx.x >> 5;
    if (lane == 0) wsum[wid] = v;
    __syncthreads();
    if (wid == 0) {
        int s = wsum[lane];
#pragma unroll
        for (int off = 16; off > 0; off >>= 1)
            s += __shfl_xor_sync(0xFFFFFFFFu, s, off);
        if (lane == 0) g_bsum[blockIdx.x] = s;
    }
}

__global__ void k_scan_wr(int n, int e, int nb) {
    __shared__ int wsum[32];
    __shared__ int sboff;
    int lane = threadIdx.x & 31, wid = threadIdx.x >> 5;

    if (wid == 0) {
        int acc = 0;
        for (int j = lane; j < nb; j += 32)
            acc += (j < blockIdx.x) ? g_bsum[j] : 0;
#pragma unroll
        for (int off = 16; off > 0; off >>= 1)
            acc += __shfl_xor_sync(0xFFFFFFFFu, acc, off);
        if (lane == 0) sboff = acc;
    }

    int i = blockIdx.x * 1024 + threadIdx.x;
    int v = (i < n) ? g_deg[i] : 0;
    int x = v;
#pragma unroll
    for (int off = 1; off < 32; off <<= 1) {
        int y = __shfl_up_sync(0xFFFFFFFFu, x, off);
        if (lane >= off) x += y;
    }
    if (lane == 31) wsum[wid] = x;
    __syncthreads();
    if (wid == 0) {
        int w = wsum[lane];
#pragma unroll
        for (int off = 1; off < 32; off <<= 1) {
            int y = __shfl_up_sync(0xFFFFFFFFu, w, off);
            if (lane >= off) w += y;
        }
        wsum[lane] = w;
    }
    __syncthreads();
    int excl = x - v + ((wid > 0) ? wsum[wid - 1] : 0) + sboff;
    if (i < n) { g_rowptr[i] = excl; g_deg[i] = 0; }
    if (i == n) g_rowptr[n] = e;
}

// ---------------- scatter (rank-based, no atomics) ----------------
__global__ void k_scatter(const int* __restrict__ src, const int* __restrict__ dst, int e) {
    int i = blockIdx.x * blockDim.x + threadIdx.x;
    if (i >= e) return;
    int p = g_rowptr[dst[i]] + g_rank[i];
    g_csrsrc[p] = src[i];
}

// ---------------- attention layer 1: 8 lanes/node, prefetched (kept from R12) ----------------
__global__ void k_attn1(int n) {
    int gt = blockIdx.x * blockDim.x + threadIdx.x;
    int node = gt >> 3;
    int sub = gt & 7;
    bool valid = (node < n);

    float4 cf0, cf1, cf2, cf3;
    int beg = 0, end = 0;
    if (valid) {
        cf0 = g_cf[node * 4 + 0];
        cf1 = g_cf[node * 4 + 1];
        cf2 = g_cf[node * 4 + 2];
        cf3 = g_cf[node * 4 + 3];
        beg = g_rowptr[node];
        end = g_rowptr[node + 1];
    }

    float4 ds0 = make_float4(0.f, 0.f, 0.f, 0.f);
    float4 ds1 = make_float4(0.f, 0.f, 0.f, 0.f);
    float4 ds2 = make_float4(0.f, 0.f, 0.f, 0.f);
    float4 ds3 = make_float4(0.f, 0.f, 0.f, 0.f);

    int i = beg + sub;
    float4 xs_c = make_float4(0.f, 0.f, 0.f, 0.f);
    if (i < end) xs_c = g_x4[g_csrsrc[i]];
    while (i < end) {
        int i2 = i + 8;
        float4 xs_n;
        if (i2 < end) xs_n = g_x4[g_csrsrc[i2]];
        float4 xs = xs_c;
        float w0 = __expf(cf0.w + cf0.x * xs.x + cf0.y * xs.y + cf0.z * xs.z);
        float w1 = __expf(cf1.w + cf1.x * xs.x + cf1.y * xs.y + cf1.z * xs.z);
        float w2 = __expf(cf2.w + cf2.x * xs.x + cf2.y * xs.y + cf2.z * xs.z);
        float w3 = __expf(cf3.w + cf3.x * xs.x + cf3.y * xs.y + cf3.z * xs.z);
        ds0.x += w0; ds0.y += w0 * xs.x; ds0.z += w0 * xs.y; ds0.w += w0 * xs.z;
        ds1.x += w1; ds1.y += w1 * xs.x; ds1.z += w1 * xs.y; ds1.w += w1 * xs.z;
        ds2.x += w2; ds2.y += w2 * xs.x; ds2.z += w2 * xs.y; ds2.w += w2 * xs.z;
        ds3.x += w3; ds3.y += w3 * xs.x; ds3.z += w3 * xs.y; ds3.w += w3 * xs.z;
        xs_c = xs_n;
        i = i2;
    }

#pragma unroll
    for (int off = 1; off <= 4; off <<= 1) {
        ds0.x += __shfl_xor_sync(0xFFFFFFFFu, ds0.x, off);
        ds0.y += __shfl_xor_sync(0xFFFFFFFFu, ds0.y, off);
        ds0.z += __shfl_xor_sync(0xFFFFFFFFu, ds0.z, off);
        ds0.w += __shfl_xor_sync(0xFFFFFFFFu, ds0.w, off);
        ds1.x += __shfl_xor_sync(0xFFFFFFFFu, ds1.x, off);
        ds1.y += __shfl_xor_sync(0xFFFFFFFFu, ds1.y, off);
        ds1.z += __shfl_xor_sync(0xFFFFFFFFu, ds1.z, off);
        ds1.w += __shfl_xor_sync(0xFFFFFFFFu, ds1.w, off);
        ds2.x += __shfl_xor_sync(0xFFFFFFFFu, ds2.x, off);
        ds2.y += __shfl_xor_sync(0xFFFFFFFFu, ds2.y, off);
        ds2.z += __shfl_xor_sync(0xFFFFFFFFu, ds2.z, off);
        ds2.w += __shfl_xor_sync(0xFFFFFFFFu, ds2.w, off);
        ds3.x += __shfl_xor_sync(0xFFFFFFFFu, ds3.x, off);
        ds3.y += __shfl_xor_sync(0xFFFFFFFFu, ds3.y, off);
        ds3.z += __shfl_xor_sync(0xFFFFFFFFu, ds3.z, off);
        ds3.w += __shfl_xor_sync(0xFFFFFFFFu, ds3.w, off);
    }

    if (valid && sub < 4) {
        float4 myds = (sub == 0) ? ds0 : (sub == 1) ? ds1 : (sub == 2) ? ds2 : ds3;
        g_ds[node * 4 + sub] = myds;
    }
}

// ---------------- layer 2 projection: 32 nodes/block, fused layer-1 epilogue ----------------
__global__ void __launch_bounds__(1024)
k_gemm2(const float* __restrict__ Wv1, const float* __restrict__ bv1,
        const float* __restrict__ Ws1, const float* __restrict__ bs1,
        const float* __restrict__ Wq, const float* __restrict__ bq,
        const float* __restrict__ Wk, const float* __restrict__ bk,
        const float* __restrict__ Wv, const float* __restrict__ bv,
        const float* __restrict__ Ws, const float* __restrict__ bs,
        int n) {
    __shared__ float  shH[32][64];
    __shared__ float  shW2[4][390];
    __shared__ float  shB2[4][6];
    __shared__ float  shWv[192], shBv[64], shWs[192], shBs[64];
    __shared__ float4 shDS[128];
    __shared__ float4 shX[32];
    int tid = threadIdx.x;
    int blk = blockIdx.x;

    for (int i = tid; i < 384 * 4; i += 1024) {
        int mm = i / 384, r = i % 384;
        const float* W = (mm == 0) ? Wq : (mm == 1) ? Wk : (mm == 2) ? Wv : Ws;
        shW2[mm][r] = W[r];
    }
    if (tid < 24) {
        int mm = tid / 6, cc = tid % 6;
        const float* b = (mm == 0) ? bq : (mm == 1) ? bk : (mm == 2) ? bv : bs;
        shB2[mm][cc] = b[cc];
    }
    if (tid < 192) { shWv[tid] = Wv1[tid]; shWs[tid] = Ws1[tid]; }
    else if (tid < 256) { shBv[tid - 192] = bv1[tid - 192]; shBs[tid - 192] = bs1[tid - 192]; }
    if (tid < 128) {
        int gidx = blk * 128 + tid;
        shDS[tid] = (gidx < n * 4) ? g_ds[gidx] : make_float4(0.f, 0.f, 0.f, 0.f);
    }
    if (tid < 32) {
        int node = blk * 32 + tid;
        shX[tid] = (node < n) ? g_x4[node] : make_float4(0.f, 0.f, 0.f, 0.f);
    }
    __syncthreads();

#pragma unroll
    for (int r = 0; r < 2; r++) {
        int idx = tid + r * 1024;
        int local = idx >> 6, c = idx & 63;
        float4 ds = shDS[local * 4 + (c >> 4)];
        float4 xt = shX[local];
        float num = shBv[c] * ds.x + shWv[c] * ds.y + shWv[64 + c] * ds.z + shWv[128 + c] * ds.w;
        float val = num / (ds.x + 1e-16f)
                  + shBs[c] + xt.x * shWs[c] + xt.y * shWs[64 + c] + xt.z * shWs[128 + c];
        shH[local][c] = fmaxf(val, 0.f);
    }
    __syncthreads();

    int w = tid >> 5;
    int lane = tid & 31;
    int node = blk * 32 + w;
    if (node >= n || lane >= 24) return;
    int mm = lane / 6, cc = lane % 6;
    float acc = shB2[mm][cc];
#pragma unroll
    for (int k = 0; k < 64; k++) acc += shH[w][k] * shW2[mm][k * 6 + cc];
    if (mm == 0)      g_qs[node * 16 + cc]      = acc * 0.4082482904638631f;
    else if (mm == 1) g_kvh[node * 16 + cc]     = __float2half(acc);
    else if (mm == 2) g_kvh[node * 16 + 6 + cc] = __float2half(acc);
    else              g_qs[node * 16 + 8 + cc]  = acc;
}

// ---------------- attention layer 2 + pooling + output (4 lanes/node, R11 form) ----------------
__global__ void k_attn2_pool(const int* __restrict__ batch, int n, float* __restrict__ out) {
    __shared__ float ssum[GG * 6];
    __shared__ float scnt[GG];
    __shared__ int   sflag[GG];
    __shared__ int   slast;
    int tid = threadIdx.x;
    for (int i = tid; i < GG * 6; i += blockDim.x) ssum[i] = 0.f;
    for (int i = tid; i < GG; i += blockDim.x) { scnt[i] = 0.f; sflag[i] = 0; }
    __syncthreads();

    int gt = blockIdx.x * blockDim.x + tid;
    int node = gt >> 2;
    int sub = gt & 3;
    bool valid = (node < n);

    float4 qa = make_float4(0.f, 0.f, 0.f, 0.f);
    float2 qb = make_float2(0.f, 0.f);
    int beg = 0, end = 0;
    if (valid) {
        qa = *reinterpret_cast<const float4*>(g_qs + node * 16);
        qb = *reinterpret_cast<const float2*>(g_qs + node * 16 + 4);
        beg = g_rowptr[node];
        end = g_rowptr[node + 1];
    }

    const uint4* kv = reinterpret_cast<const uint4*>(g_kvh);

    float den = 0.f;
    float a0 = 0.f, a1 = 0.f, a2 = 0.f, a3 = 0.f, a4 = 0.f, a5 = 0.f;

    int i = beg + sub;
    uint4 r0c = make_uint4(0, 0, 0, 0), r1c = make_uint4(0, 0, 0, 0);
    if (i < end) {
        int s = g_csrsrc[i];
        r0c = kv[s * 2 + 0];
        r1c = kv[s * 2 + 1];
    }
    while (i < end) {
        int i2 = i + 4;
        uint4 r0n, r1n;
        if (i2 < end) {
            int s2 = g_csrsrc[i2];
            r0n = kv[s2 * 2 + 0];
            r1n = kv[s2 * 2 + 1];
        }
        float2 k01 = __half22float2(*reinterpret_cast<const __half2*>(&r0c.x));
        float2 k23 = __half22float2(*reinterpret_cast<const __half2*>(&r0c.y));
        float2 k45 = __half22float2(*reinterpret_cast<const __half2*>(&r0c.z));
        float2 v01 = __half22float2(*reinterpret_cast<const __half2*>(&r0c.w));
        float2 v23 = __half22float2(*reinterpret_cast<const __half2*>(&r1c.x));
        float2 v45 = __half22float2(*reinterpret_cast<const __half2*>(&r1c.y));
        float l = qa.x * k01.x + qa.y * k01.y + qa.z * k23.x + qa.w * k23.y
                + qb.x * k45.x + qb.y * k45.y;
        float w = __expf(l);
        den += w;
        a0 += w * v01.x; a1 += w * v01.y;
        a2 += w * v23.x; a3 += w * v23.y;
        a4 += w * v45.x; a5 += w * v45.y;
        r0c = r0n; r1c = r1n;
        i = i2;
    }

#pragma unroll
    for (int off = 1; off <= 2; off <<= 1) {
        den += __shfl_xor_sync(0xFFFFFFFFu, den, off);
        a0 += __shfl_xor_sync(0xFFFFFFFFu, a0, off);
        a1 += __shfl_xor_sync(0xFFFFFFFFu, a1, off);
        a2 += __shfl_xor_sync(0xFFFFFFFFu, a2, off);
        a3 += __shfl_xor_sync(0xFFFFFFFFu, a3, off);
        a4 += __shfl_xor_sync(0xFFFFFFFFu, a4, off);
        a5 += __shfl_xor_sync(0xFFFFFFFFu, a5, off);
    }

    if (valid && sub == 0) {
        float inv = 1.f / (den + 1e-16f);
        int g = __ldg(&batch[node]);
        const float* sp = g_qs + node * 16 + 8;
        atomicAdd(&ssum[g * 6 + 0], a0 * inv + sp[0]);
        atomicAdd(&ssum[g * 6 + 1], a1 * inv + sp[1]);
        atomicAdd(&ssum[g * 6 + 2], a2 * inv + sp[2]);
        atomicAdd(&ssum[g * 6 + 3], a3 * inv + sp[3]);
        atomicAdd(&ssum[g * 6 + 4], a4 * inv + sp[4]);
        atomicAdd(&ssum[g * 6 + 5], a5 * inv + sp[5]);
        atomicAdd(&scnt[g], 1.f);
        sflag[g] = 1;
    }
    __syncthreads();
    for (int g = tid; g < GG; g += blockDim.x) {
        if (sflag[g]) {
            atomicAdd(&g_cnt[g], scnt[g]);
#pragma unroll
            for (int c = 0; c < 6; c++)
                atomicAdd(&g_sums[g * 6 + c], ssum[g * 6 + c]);
        }
    }
    __syncthreads();
    if (tid == 0) {
        __threadfence();
        int t = atomicAdd(&g_ticket, 1);
        slast = (t == (int)gridDim.x - 1) ? 1 : 0;
    }
    __syncthreads();
    if (slast) {
        __threadfence();
        int g = tid;
        if (g < GG) {
            float cnt = fmaxf(g_cnt[g], 1.f);
            float p[6];
            float m = -INFINITY;
#pragma unroll
            for (int c = 0; c < 6; c++) { p[c] = g_sums[g * 6 + c] / cnt; m = fmaxf(m, p[c]); }
            float s = 0.f;
#pragma unroll
            for (int c = 0; c < 6; c++) s += expf(p[c] - m);
            float lse = m + logf(s);
#pragma unroll
            for (int c = 0; c < 6; c++) out[g * 6 + c] = p[c] - lse;
        }
        __syncthreads();
        for (int i2 = tid; i2 < GG * 6; i2 += blockDim.x) g_sums[i2] = 0.f;
        for (int i2 = tid; i2 < GG; i2 += blockDim.x) g_cnt[i2] = 0.f;
        if (tid == 0) g_ticket = 0;
    }
}

// ---------------- launch ----------------
extern "C" void kernel_launch(void* const* d_in, const int* in_sizes, int n_in,
                              void* d_out, int out_size) {
    const float* x    = (const float*)d_in[0];
    const int*   ei   = (const int*)  d_in[1];
    const int*   batch= (const int*)  d_in[2];
    const float* Wq1  = (const float*)d_in[3];
    const float* bq1  = (const float*)d_in[4];
    const float* Wk1  = (const float*)d_in[5];
    const float* bk1  = (const float*)d_in[6];
    const float* Wv1  = (const float*)d_in[7];
    const float* bv1  = (const float*)d_in[8];
    const float* Ws1  = (const float*)d_in[9];
    const float* bs1  = (const float*)d_in[10];
    const float* Wq2  = (const float*)d_in[11];
    const float* bq2  = (const float*)d_in[12];
    const float* Wk2  = (const float*)d_in[13];
    const float* bk2  = (const float*)d_in[14];
    const float* Wv2  = (const float*)d_in[15];
    const float* bv2  = (const float*)d_in[16];
    const float* Ws2  = (const float*)d_in[17];
    const float* bs2  = (const float*)d_in[18];
    float* out = (float*)d_out;

    int N = in_sizes[0] / 3;
    int E = in_sizes[1] / 2;
    const int* src = ei;
    const int* dst = ei + E;

    const int B = 256;
    int NB = (N + 1024) / 1024;   // covers i == N for rowptr[N]

    k_prep_hist<<<(E + B - 1) / B, B>>>(x, dst, Wq1, bq1, Wk1, bk1, N, E);
    k_scan_blk<<<NB, 1024>>>(N);
    k_scan_wr<<<NB, 1024>>>(N, E, NB);
    k_scatter<<<(E + B - 1) / B, B>>>(src, dst, E);
    k_attn1<<<(N * 8 + B - 1) / B, B>>>(N);
    k_gemm2<<<(N + 31) / 32, 1024>>>(Wv1, bv1, Ws1, bs1,
                                     Wq2, bq2, Wk2, bk2, Wv2, bv2, Ws2, bs2, N);
    k_attn2_pool<<<(N * 4 + B - 1) / B, B>>>(batch, N, out);
}

// round 15
// speedup vs baseline: 1.1186x; 1.1035x over previous
#include <cuda_runtime.h>
#include <cuda_fp16.h>
#include <math.h>

#define NN 100000
#define EE 3200000
#define GG 64

// ---------------- static device scratch (zero-initialized at module load) ----------------
__device__ float4 g_x4[NN];          // padded x
__device__ float4 g_cf[NN * 4];      // per (node,head): (e0,e1,e2,d0) pre-scaled

__device__ __half g_kvh[NN * 16];    // 32B/node: [0..5]=k2 half, [6..11]=v2 half, pad
__device__ float  g_qs[NN * 16];     // [0..5]=q2 (pre-scaled), [8..13]=s2

__device__ int g_deg   [NN];         // invariant: zero on kernel_launch entry
__device__ int g_rowptr[NN + 1];
__device__ int g_rank  [EE];
__device__ int g_csrsrc[EE];
__device__ int g_bsum[128];
__device__ int g_ticket;             // invariant: zero on entry

__device__ float g_sums[GG * 6];     // invariant: zero on entry
__device__ float g_cnt [GG];         // invariant: zero on entry

// ---------------- fused prep + hist ----------------
__global__ void k_prep_hist(const float* __restrict__ x,
                            const int* __restrict__ dst,
                            const float* __restrict__ Wq, const float* __restrict__ bq,
                            const float* __restrict__ Wk, const float* __restrict__ bk,
                            int n, int e) {
    int idx = blockIdx.x * blockDim.x + threadIdx.x;
    if (idx < e)
        g_rank[idx] = atomicAdd(&g_deg[dst[idx]], 1);
    if (idx >= n * 4) return;
    int node = idx >> 2, h = idx & 3;
    float x0 = __ldg(&x[node * 3 + 0]);
    float x1 = __ldg(&x[node * 3 + 1]);
    float x2 = __ldg(&x[node * 3 + 2]);
    if (h == 0)
        g_x4[node] = make_float4(x0, x1, x2, 0.f);
    float d0 = 0.f, e0 = 0.f, e1 = 0.f, e2 = 0.f;
    int base = h * 16;
#pragma unroll
    for (int c = 0; c < 16; c++) {
        int cc = base + c;
        float qc = bq[cc] + x0 * Wq[cc] + x1 * Wq[64 + cc] + x2 * Wq[128 + cc];
        d0 += qc * bk[cc];
        e0 += qc * Wk[cc];
        e1 += qc * Wk[64 + cc];
        e2 += qc * Wk[128 + cc];
    }
    g_cf[idx] = make_float4(e0 * 0.25f, e1 * 0.25f, e2 * 0.25f, d0 * 0.25f);
}

// ---------------- two-kernel scan ----------------
__global__ void k_scan_blk(int n) {
    __shared__ int wsum[32];
    int i = blockIdx.x * 1024 + threadIdx.x;
    int v = (i < n) ? g_deg[i] : 0;
#pragma unroll
    for (int off = 16; off > 0; off >>= 1)
        v += __shfl_xor_sync(0xFFFFFFFFu, v, off);
    int lane = threadIdx.x & 31, wid = threadIdx.x >> 5;
    if (lane == 0) wsum[wid] = v;
    __syncthreads();
    if (wid == 0) {
        int s = wsum[lane];
#pragma unroll
        for (int off = 16; off > 0; off >>= 1)
            s += __shfl_xor_sync(0xFFFFFFFFu, s, off);
        if (lane == 0) g_bsum[blockIdx.x] = s;
    }
}

__global__ void k_scan_wr(int n, int e, int nb) {
    __shared__ int wsum[32];
    __shared__ int sboff;
    int lane = threadIdx.x & 31, wid = threadIdx.x >> 5;

    if (wid == 0) {
        int acc = 0;
        for (int j = lane; j < nb; j += 32)
            acc += (j < blockIdx.x) ? g_bsum[j] : 0;
#pragma unroll
        for (int off = 16; off > 0; off >>= 1)
            acc += __shfl_xor_sync(0xFFFFFFFFu, acc, off);
        if (lane == 0) sboff = acc;
    }

    int i = blockIdx.x * 1024 + threadIdx.x;
    int v = (i < n) ? g_deg[i] : 0;
    int x = v;
#pragma unroll
    for (int off = 1; off < 32; off <<= 1) {
        int y = __shfl_up_sync(0xFFFFFFFFu, x, off);
        if (lane >= off) x += y;
    }
    if (lane == 31) wsum[wid] = x;
    __syncthreads();
    if (wid == 0) {
        int w = wsum[lane];
#pragma unroll
        for (int off = 1; off < 32; off <<= 1) {
            int y = __shfl_up_sync(0xFFFFFFFFu, w, off);
            if (lane >= off) w += y;
        }
        wsum[lane] = w;
    }
    __syncthreads();
    int excl = x - v + ((wid > 0) ? wsum[wid - 1] : 0) + sboff;
    if (i < n) { g_rowptr[i] = excl; g_deg[i] = 0; }
    if (i == n) g_rowptr[n] = e;
}

// ---------------- scatter (rank-based, no atomics) ----------------
__global__ void k_scatter(const int* __restrict__ src, const int* __restrict__ dst, int e) {
    int i = blockIdx.x * blockDim.x + threadIdx.x;
    if (i >= e) return;
    int p = g_rowptr[dst[i]] + g_rank[i];
    g_csrsrc[p] = src[i];
}

// ---------------- fused attention layer 1 + layer-2 projection ----------------
// 256 threads = 32 octets = 32 nodes per block.
// Phase A: 8 lanes/node edge loop + merge (all lanes end with full ds0..3).
// Phase B: reconstruct h[32][64] in shared (layer-1 epilogue).
// Phase C: project to q2 (scaled) / k2,v2 (half) / s2, 8 lanes x 3 outputs per node.
__global__ void __launch_bounds__(256)
k_attn1_proj(const float* __restrict__ Wv1, const float* __restrict__ bv1,
             const float* __restrict__ Ws1, const float* __restrict__ bs1,
             const float* __restrict__ Wq, const float* __restrict__ bq,
             const float* __restrict__ Wk, const float* __restrict__ bk,
             const float* __restrict__ Wv, const float* __restrict__ bv,
             const float* __restrict__ Ws, const float* __restrict__ bs,
             int n) {
    __shared__ float  shH[32][64];     // 8 KB
    __shared__ float  shW2[4][390];    // layer-2 weights (384 used, padded)
    __shared__ float  shB2[4][6];
    __shared__ float  shWv[192], shBv[64], shWs[192], shBs[64];
    __shared__ float4 shDS[32][4];     // per-node per-head (den, sx)
    __shared__ float4 shX[32];

    int tid = threadIdx.x;
    int blk = blockIdx.x;

    // stage weights
    for (int i = tid; i < 384 * 4; i += 256) {
        int mm = i / 384, r = i % 384;
        const float* W = (mm == 0) ? Wq : (mm == 1) ? Wk : (mm == 2) ? Wv : Ws;
        shW2[mm][r] = W[r];
    }
    if (tid < 24) {
        int mm = tid / 6, cc = tid % 6;
        const float* b = (mm == 0) ? bq : (mm == 1) ? bk : (mm == 2) ? bv : bs;
        shB2[mm][cc] = b[cc];
    }
    if (tid < 192) { shWv[tid] = Wv1[tid]; shWs[tid] = Ws1[tid]; }
    else if (tid < 256) { shBv[tid - 192] = bv1[tid - 192]; shBs[tid - 192] = bs1[tid - 192]; }
    if (tid < 32) {
        int node = blk * 32 + tid;
        shX[tid] = (node < n) ? g_x4[node] : make_float4(0.f, 0.f, 0.f, 0.f);
    }

    // ---- Phase A: edge loop (8 lanes per node) ----
    int local = tid >> 3;              // node within block
    int sub = tid & 7;
    int node = blk * 32 + local;
    bool valid = (node < n);

    float4 cf0, cf1, cf2, cf3;
    int beg = 0, end = 0;
    if (valid) {
        cf0 = g_cf[node * 4 + 0];
        cf1 = g_cf[node * 4 + 1];
        cf2 = g_cf[node * 4 + 2];
        cf3 = g_cf[node * 4 + 3];
        beg = g_rowptr[node];
        end = g_rowptr[node + 1];
    }

    float4 ds0 = make_float4(0.f, 0.f, 0.f, 0.f);
    float4 ds1 = make_float4(0.f, 0.f, 0.f, 0.f);
    float4 ds2 = make_float4(0.f, 0.f, 0.f, 0.f);
    float4 ds3 = make_float4(0.f, 0.f, 0.f, 0.f);

    int i = beg + sub;
    float4 xs_c = make_float4(0.f, 0.f, 0.f, 0.f);
    if (i < end) xs_c = g_x4[g_csrsrc[i]];
    while (i < end) {
        int i2 = i + 8;
        float4 xs_n;
        if (i2 < end) xs_n = g_x4[g_csrsrc[i2]];
        float4 xs = xs_c;
        float w0 = __expf(cf0.w + cf0.x * xs.x + cf0.y * xs.y + cf0.z * xs.z);
        float w1 = __expf(cf1.w + cf1.x * xs.x + cf1.y * xs.y + cf1.z * xs.z);
        float w2 = __expf(cf2.w + cf2.x * xs.x + cf2.y * xs.y + cf2.z * xs.z);
        float w3 = __expf(cf3.w + cf3.x * xs.x + cf3.y * xs.y + cf3.z * xs.z);
        ds0.x += w0; ds0.y += w0 * xs.x; ds0.z += w0 * xs.y; ds0.w += w0 * xs.z;
        ds1.x += w1; ds1.y += w1 * xs.x; ds1.z += w1 * xs.y; ds1.w += w1 * xs.z;
        ds2.x += w2; ds2.y += w2 * xs.x; ds2.z += w2 * xs.y; ds2.w += w2 * xs.z;
        ds3.x += w3; ds3.y += w3 * xs.x; ds3.z += w3 * xs.y; ds3.w += w3 * xs.z;
        xs_c = xs_n;
        i = i2;
    }

#pragma unroll
    for (int off = 1; off <= 4; off <<= 1) {
        ds0.x += __shfl_xor_sync(0xFFFFFFFFu, ds0.x, off);
        ds0.y += __shfl_xor_sync(0xFFFFFFFFu, ds0.y, off);
        ds0.z += __shfl_xor_sync(0xFFFFFFFFu, ds0.z, off);
        ds0.w += __shfl_xor_sync(0xFFFFFFFFu, ds0.w, off);
        ds1.x += __shfl_xor_sync(0xFFFFFFFFu, ds1.x, off);
        ds1.y += __shfl_xor_sync(0xFFFFFFFFu, ds1.y, off);
        ds1.z += __shfl_xor_sync(0xFFFFFFFFu, ds1.z, off);
        ds1.w += __shfl_xor_sync(0xFFFFFFFFu, ds1.w, off);
        ds2.x += __shfl_xor_sync(0xFFFFFFFFu, ds2.x, off);
        ds2.y += __shfl_xor_sync(0xFFFFFFFFu, ds2.y, off);
        ds2.z += __shfl_xor_sync(0xFFFFFFFFu, ds2.z, off);
        ds2.w += __shfl_xor_sync(0xFFFFFFFFu, ds2.w, off);
        ds3.x += __shfl_xor_sync(0xFFFFFFFFu, ds3.x, off);
        ds3.y += __shfl_xor_sync(0xFFFFFFFFu, ds3.y, off);
        ds3.z += __shfl_xor_sync(0xFFFFFFFFu, ds3.z, off);
        ds3.w += __shfl_xor_sync(0xFFFFFFFFu, ds3.w, off);
    }

    if (sub < 4) {
        float4 myds = (sub == 0) ? ds0 : (sub == 1) ? ds1 : (sub == 2) ? ds2 : ds3;
        shDS[local][sub] = myds;     // valid nodes only matter; junk for tail is masked below
    }
    __syncthreads();

    // ---- Phase B: reconstruct h (2048 values, 8 per thread) ----
#pragma unroll
    for (int r = 0; r < 8; r++) {
        int idx = tid + r * 256;
        int lo = idx >> 6, c = idx & 63;
        float4 ds = shDS[lo][c >> 4];
        float4 xt = shX[lo];
        float num = shBv[c] * ds.x + shWv[c] * ds.y + shWv[64 + c] * ds.z + shWv[128 + c] * ds.w;
        float val = num / (ds.x + 1e-16f)
                  + shBs[c] + xt.x * shWs[c] + xt.y * shWs[64 + c] + xt.z * shWs[128 + c];
        shH[lo][c] = fmaxf(val, 0.f);
    }
    __syncthreads();

    // ---- Phase C: project: 8 lanes x 3 outputs per node ----
    if (!valid) return;
#pragma unroll
    for (int t = 0; t < 3; t++) {
        int o = sub * 3 + t;           // 0..23
        int mm = o / 6, cc = o % 6;
        float acc = shB2[mm][cc];
#pragma unroll
        for (int k = 0; k < 64; k++) acc += shH[local][k] * shW2[mm][k * 6 + cc];
        if (mm == 0)      g_qs[node * 16 + cc]      = acc * 0.4082482904638631f;
        else if (mm == 1) g_kvh[node * 16 + cc]     = __float2half(acc);
        else if (mm == 2) g_kvh[node * 16 + 6 + cc] = __float2half(acc);
        else              g_qs[node * 16 + 8 + cc]  = acc;
    }
}

// ---------------- attention layer 2 + pooling + output (4 lanes/node, ticket) ----------------
__global__ void k_attn2_pool(const int* __restrict__ batch, int n, float* __restrict__ out) {
    __shared__ float ssum[GG * 6];
    __shared__ float scnt[GG];
    __shared__ int   sflag[GG];
    __shared__ int   slast;
    int tid = threadIdx.x;
    for (int i = tid; i < GG * 6; i += blockDim.x) ssum[i] = 0.f;
    for (int i = tid; i < GG; i += blockDim.x) { scnt[i] = 0.f; sflag[i] = 0; }
    __syncthreads();

    int gt = blockIdx.x * blockDim.x + tid;
    int node = gt >> 2;
    int sub = gt & 3;
    bool valid = (node < n);

    float4 qa = make_float4(0.f, 0.f, 0.f, 0.f);
    float2 qb = make_float2(0.f, 0.f);
    int beg = 0, end = 0;
    if (valid) {
        qa = *reinterpret_cast<const float4*>(g_qs + node * 16);
        qb = *reinterpret_cast<const float2*>(g_qs + node * 16 + 4);
        beg = g_rowptr[node];
        end = g_rowptr[node + 1];
    }

    const uint4* kv = reinterpret_cast<const uint4*>(g_kvh);

    float den = 0.f;
    float a0 = 0.f, a1 = 0.f, a2 = 0.f, a3 = 0.f, a4 = 0.f, a5 = 0.f;

    int i = beg + sub;
    uint4 r0c = make_uint4(0, 0, 0, 0), r1c = make_uint4(0, 0, 0, 0);
    if (i < end) {
        int s = g_csrsrc[i];
        r0c = kv[s * 2 + 0];
        r1c = kv[s * 2 + 1];
    }
    while (i < end) {
        int i2 = i + 4;
        uint4 r0n, r1n;
        if (i2 < end) {
            int s2 = g_csrsrc[i2];
            r0n = kv[s2 * 2 + 0];
            r1n = kv[s2 * 2 + 1];
        }
        float2 k01 = __half22float2(*reinterpret_cast<const __half2*>(&r0c.x));
        float2 k23 = __half22float2(*reinterpret_cast<const __half2*>(&r0c.y));
        float2 k45 = __half22float2(*reinterpret_cast<const __half2*>(&r0c.z));
        float2 v01 = __half22float2(*reinterpret_cast<const __half2*>(&r0c.w));
        float2 v23 = __half22float2(*reinterpret_cast<const __half2*>(&r1c.x));
        float2 v45 = __half22float2(*reinterpret_cast<const __half2*>(&r1c.y));
        float l = qa.x * k01.x + qa.y * k01.y + qa.z * k23.x + qa.w * k23.y
                + qb.x * k45.x + qb.y * k45.y;
        float w = __expf(l);
        den += w;
        a0 += w * v01.x; a1 += w * v01.y;
        a2 += w * v23.x; a3 += w * v23.y;
        a4 += w * v45.x; a5 += w * v45.y;
        r0c = r0n; r1c = r1n;
        i = i2;
    }

#pragma unroll
    for (int off = 1; off <= 2; off <<= 1) {
        den += __shfl_xor_sync(0xFFFFFFFFu, den, off);
        a0 += __shfl_xor_sync(0xFFFFFFFFu, a0, off);
        a1 += __shfl_xor_sync(0xFFFFFFFFu, a1, off);
        a2 += __shfl_xor_sync(0xFFFFFFFFu, a2, off);
        a3 += __shfl_xor_sync(0xFFFFFFFFu, a3, off);
        a4 += __shfl_xor_sync(0xFFFFFFFFu, a4, off);
        a5 += __shfl_xor_sync(0xFFFFFFFFu, a5, off);
    }

    if (valid && sub == 0) {
        float inv = 1.f / (den + 1e-16f);
        int g = __ldg(&batch[node]);
        const float* sp = g_qs + node * 16 + 8;
        atomicAdd(&ssum[g * 6 + 0], a0 * inv + sp[0]);
        atomicAdd(&ssum[g * 6 + 1], a1 * inv + sp[1]);
        atomicAdd(&ssum[g * 6 + 2], a2 * inv + sp[2]);
        atomicAdd(&ssum[g * 6 + 3], a3 * inv + sp[3]);
        atomicAdd(&ssum[g * 6 + 4], a4 * inv + sp[4]);
        atomicAdd(&ssum[g * 6 + 5], a5 * inv + sp[5]);
        atomicAdd(&scnt[g], 1.f);
        sflag[g] = 1;
    }
    __syncthreads();
    for (int g = tid; g < GG; g += blockDim.x) {
        if (sflag[g]) {
            atomicAdd(&g_cnt[g], scnt[g]);
#pragma unroll
            for (int c = 0; c < 6; c++)
                atomicAdd(&g_sums[g * 6 + c], ssum[g * 6 + c]);
        }
    }
    __syncthreads();
    if (tid == 0) {
        __threadfence();
        int t = atomicAdd(&g_ticket, 1);
        slast = (t == (int)gridDim.x - 1) ? 1 : 0;
    }
    __syncthreads();
    if (slast) {
        __threadfence();
        int g = tid;
        if (g < GG) {
            float cnt = fmaxf(g_cnt[g], 1.f);
            float p[6];
            float m = -INFINITY;
#pragma unroll
            for (int c = 0; c < 6; c++) { p[c] = g_sums[g * 6 + c] / cnt; m = fmaxf(m, p[c]); }
            float s = 0.f;
#pragma unroll
            for (int c = 0; c < 6; c++) s += expf(p[c] - m);
            float lse = m + logf(s);
#pragma unroll
            for (int c = 0; c < 6; c++) out[g * 6 + c] = p[c] - lse;
        }
        __syncthreads();
        for (int i2 = tid; i2 < GG * 6; i2 += blockDim.x) g_sums[i2] = 0.f;
        for (int i2 = tid; i2 < GG; i2 += blockDim.x) g_cnt[i2] = 0.f;
        if (tid == 0) g_ticket = 0;
    }
}

// ---------------- launch ----------------
extern "C" void kernel_launch(void* const* d_in, const int* in_sizes, int n_in,
                              void* d_out, int out_size) {
    const float* x    = (const float*)d_in[0];
    const int*   ei   = (const int*)  d_in[1];
    const int*   batch= (const int*)  d_in[2];
    const float* Wq1  = (const float*)d_in[3];
    const float* bq1  = (const float*)d_in[4];
    const float* Wk1  = (const float*)d_in[5];
    const float* bk1  = (const float*)d_in[6];
    const float* Wv1  = (const float*)d_in[7];
    const float* bv1  = (const float*)d_in[8];
    const float* Ws1  = (const float*)d_in[9];
    const float* bs1  = (const float*)d_in[10];
    const float* Wq2  = (const float*)d_in[11];
    const float* bq2  = (const float*)d_in[12];
    const float* Wk2  = (const float*)d_in[13];
    const float* bk2  = (const float*)d_in[14];
    const float* Wv2  = (const float*)d_in[15];
    const float* bv2  = (const float*)d_in[16];
    const float* Ws2  = (const float*)d_in[17];
    const float* bs2  = (const float*)d_in[18];
    float* out = (float*)d_out;

    int N = in_sizes[0] / 3;
    int E = in_sizes[1] / 2;
    const int* src = ei;
    const int* dst = ei + E;

    const int B = 256;
    int NB = (N + 1024) / 1024;   // covers i == N for rowptr[N]

    k_prep_hist<<<(E + B - 1) / B, B>>>(x, dst, Wq1, bq1, Wk1, bk1, N, E);
    k_scan_blk<<<NB, 1024>>>(N);
    k_scan_wr<<<NB, 1024>>>(N, E, NB);
    k_scatter<<<(E + B - 1) / B, B>>>(src, dst, E);
    k_attn1_proj<<<(N + 31) / 32, 256>>>(Wv1, bv1, Ws1, bs1,
                                         Wq2, bq2, Wk2, bk2, Wv2, bv2, Ws2, bs2, N);
    k_attn2_pool<<<(N * 4 + B - 1) / B, B>>>(batch, N, out);
}